// round 10
// baseline (speedup 1.0000x reference)
#include <cuda_runtime.h>

#define NN 50000
#define EE 800000
#define PADX 68   // 17 float4 per row: 16B-aligned rows, bank-shifted
#define NT64 (EE / 64)        // 12500 edge tiles
#define NTN ((NN + 63) >> 6)  // 782 node tiles

// persistent scratch (allocation-free rule: __device__ globals)
__device__ float g_xh[NN * 64];
__device__ float g_h [EE * 64];   // encoder hidden (relu of edge-enc layer1)
__device__ float g_m0[EE * 64];   // layer-0 edge MLP hidden
__device__ float g_agg[NN * 64];
__device__ float g_P[NN * 64];
__device__ float g_Q[NN * 64];
__device__ float g_Sh [NN * 64];  // segment sums
__device__ float g_Sm0[NN * 64];
__device__ float g_Sm1[NN * 64];
__device__ float g_deg[NN];
__device__ float g_F0[4096];      // W2e @ W1a0
__device__ float g_G1[4096];      // W2e @ W1a1
__device__ float g_H1[4096];      // W2_0 @ W1a1
__device__ float g_c0[64];        // b1_0 + b2e@W1a0
__device__ float g_c1[64];        // b1_1 + (b2e+b2_0)@W1a1
__device__ float g_cr[64];        // b2e + b2_0

__device__ __forceinline__ void red_add_v4(float* p, float4 v) {
    asm volatile("red.global.add.v4.f32 [%0], {%1,%2,%3,%4};"
                 :: "l"(p), "f"(v.x), "f"(v.y), "f"(v.z), "f"(v.w) : "memory");
}

// ---------------------------------------------------------------------------
// Node encoder: x [N,8] -> relu(x@W1+b1)@W2+b2 -> x_h [N,64]
// ---------------------------------------------------------------------------
template <int FIN>
__global__ __launch_bounds__(256) void k_encode(
    const float* __restrict__ inp, int M,
    const float* __restrict__ w1, const float* __restrict__ b1,
    const float* __restrict__ w2, const float* __restrict__ b2,
    float* __restrict__ out)
{
    extern __shared__ float sm[];
    float* sW2 = sm;
    float* sW1 = sW2 + 4096;
    float* sB1 = sW1 + FIN * 64;
    float* sB2 = sB1 + 64;
    float* sIn = sB2 + 64;
    float* h1  = sIn + 64 * FIN;
    for (int i = threadIdx.x; i < 4096; i += 256) sW2[i] = w2[i];
    for (int i = threadIdx.x; i < FIN * 64; i += 256) sW1[i] = w1[i];
    if (threadIdx.x < 64) { sB1[threadIdx.x] = b1[threadIdx.x]; sB2[threadIdx.x] = b2[threadIdx.x]; }
    __syncthreads();
    const int jo = (threadIdx.x & 15) * 4;
    const int eo = (threadIdx.x >> 4) * 4;
    const int ntiles = (M + 63) >> 6;
    for (int t = blockIdx.x; t < ntiles; t += gridDim.x) {
        const int m0 = t << 6;
        for (int idx = threadIdx.x; idx < 64 * FIN; idx += 256) {
            int m = m0 + idx / FIN;
            sIn[idx] = (m < M) ? inp[(size_t)m0 * FIN + idx] : 0.f;
        }
        __syncthreads();
        for (int idx = threadIdx.x; idx < 4096; idx += 256) {
            int ml = idx >> 6, j = idx & 63;
            float acc = sB1[j];
#pragma unroll
            for (int k = 0; k < FIN; k++) acc = fmaf(sIn[ml * FIN + k], sW1[k * 64 + j], acc);
            h1[ml * PADX + j] = fmaxf(acc, 0.f);
        }
        __syncthreads();
        float acc[4][4];
#pragma unroll
        for (int i = 0; i < 4; i++)
#pragma unroll
            for (int jj = 0; jj < 4; jj++) acc[i][jj] = sB2[jo + jj];
        for (int k4 = 0; k4 < 64; k4 += 4) {
            float a[4][4];
#pragma unroll
            for (int i = 0; i < 4; i++)
                *(float4*)a[i] = *(const float4*)(h1 + (eo + i) * PADX + k4);
#pragma unroll
            for (int kk = 0; kk < 4; kk++) {
                float4 w = *(const float4*)(sW2 + (k4 + kk) * 64 + jo);
#pragma unroll
                for (int i = 0; i < 4; i++) {
                    acc[i][0] = fmaf(a[i][kk], w.x, acc[i][0]);
                    acc[i][1] = fmaf(a[i][kk], w.y, acc[i][1]);
                    acc[i][2] = fmaf(a[i][kk], w.z, acc[i][2]);
                    acc[i][3] = fmaf(a[i][kk], w.w, acc[i][3]);
                }
            }
        }
#pragma unroll
        for (int i = 0; i < 4; i++) {
            int m = m0 + eo + i;
            if (m < M)
                *(float4*)(out + (size_t)m * 64 + jo) = make_float4(acc[i][0], acc[i][1], acc[i][2], acc[i][3]);
        }
        __syncthreads();
    }
}

// ---------------------------------------------------------------------------
// Edge encoder LAYER 1 ONLY: h = relu(ea@W1e + b1e)   [E,64]
// ---------------------------------------------------------------------------
__global__ __launch_bounds__(256) void k_ench(
    const float* __restrict__ ea,
    const float* __restrict__ w1, const float* __restrict__ b1)
{
    __shared__ float sW[256], sB[64], sIn[256];
    if (threadIdx.x < 256) sW[threadIdx.x] = w1[threadIdx.x];
    if (threadIdx.x < 64) sB[threadIdx.x] = b1[threadIdx.x];
    __syncthreads();
    for (int t = blockIdx.x; t < NT64; t += gridDim.x) {
        const int e0 = t << 6;
        sIn[threadIdx.x] = ea[(size_t)e0 * 4 + threadIdx.x];
        __syncthreads();
        for (int idx = threadIdx.x; idx < 4096; idx += 256) {
            int ml = idx >> 6, j = idx & 63;
            float acc = sB[j];
#pragma unroll
            for (int k = 0; k < 4; k++) acc = fmaf(sIn[ml * 4 + k], sW[k * 64 + j], acc);
            g_h[(size_t)(e0 + ml) * 64 + j] = fmaxf(acc, 0.f);
        }
        __syncthreads();
    }
}

// ---------------------------------------------------------------------------
// Precompute fused weights/biases (3 blocks).
//  b0: F0 = w2e@W1a0, c0, cr ; b1: G1 = w2e@W1a1, c1 ; b2: H1 = W2_0@W1a1
// ---------------------------------------------------------------------------
__global__ __launch_bounds__(256) void k_prep(
    const float* __restrict__ w2e, const float* __restrict__ b2e,
    const float* __restrict__ pe_w1, const float* __restrict__ pe_b1,
    const float* __restrict__ pe_w2, const float* __restrict__ pe_b2)
{
    __shared__ float sA[4096], sB[4096];
    const float* w1a0 = pe_w1;               // layer0 rows [0,64)
    const float* w1a1 = pe_w1 + 192 * 64;    // layer1 rows [0,64)
    const float *A, *B; float* O;
    if (blockIdx.x == 0)      { A = w2e;   B = w1a0; O = g_F0; }
    else if (blockIdx.x == 1) { A = w2e;   B = w1a1; O = g_G1; }
    else                      { A = pe_w2; B = w1a1; O = g_H1; }
    for (int i = threadIdx.x; i < 4096; i += 256) { sA[i] = A[i]; sB[i] = B[i]; }
    __syncthreads();
    for (int idx = threadIdx.x; idx < 4096; idx += 256) {
        int k = idx >> 6, j = idx & 63;
        float acc = 0.f;
#pragma unroll 8
        for (int t = 0; t < 64; t++) acc = fmaf(sA[k * 64 + t], sB[t * 64 + j], acc);
        O[idx] = acc;
    }
    if (blockIdx.x == 0 && threadIdx.x < 64) {
        int j = threadIdx.x;
        float a = pe_b1[j];
        for (int t = 0; t < 64; t++) a = fmaf(b2e[t], sB[t * 64 + j], a);
        g_c0[j] = a;
        g_cr[j] = b2e[j] + pe_b2[j];
    }
    if (blockIdx.x == 1 && threadIdx.x < 64) {
        int j = threadIdx.x;
        float a = pe_b1[64 + j];
        for (int t = 0; t < 64; t++) a = fmaf(b2e[t] + pe_b2[t], sB[t * 64 + j], a);
        g_c1[j] = a;
    }
}

// degree: deg[v] = #edges with dst==v
__global__ __launch_bounds__(256) void k_deg(const int* __restrict__ dst) {
    for (int e = blockIdx.x * 256 + threadIdx.x; e < EE; e += gridDim.x * 256)
        atomicAdd(g_deg + dst[e], 1.0f);
}

// ---------------------------------------------------------------------------
// P = x_h @ W1b + c ; Q = x_h @ W1c    (c = fused bias, device pointer)
// ---------------------------------------------------------------------------
__global__ __launch_bounds__(256) void k_pq(
    const float* __restrict__ w1b, const float* __restrict__ w1c,
    const float* __restrict__ b1)
{
    extern __shared__ float sm[];
    float* sWb = sm;
    float* sWc = sWb + 4096;
    float* sB  = sWc + 4096;
    float* xs  = sB + 64;
    for (int i = threadIdx.x; i < 4096; i += 256) { sWb[i] = w1b[i]; sWc[i] = w1c[i]; }
    if (threadIdx.x < 64) sB[threadIdx.x] = b1[threadIdx.x];
    __syncthreads();
    const int jo = (threadIdx.x & 15) * 4;
    const int eo = (threadIdx.x >> 4) * 4;
    for (int t = blockIdx.x; t < NTN; t += gridDim.x) {
        const int m0 = t << 6;
        for (int idx = threadIdx.x; idx < 1024; idx += 256) {
            int ml = idx >> 4, j4 = (idx & 15) * 4;
            int m = m0 + ml;
            float4 v = (m < NN) ? *(const float4*)(g_xh + (size_t)m * 64 + j4)
                                : make_float4(0.f, 0.f, 0.f, 0.f);
            *(float4*)(xs + ml * PADX + j4) = v;
        }
        __syncthreads();
        float ap[4][4], aq[4][4];
#pragma unroll
        for (int i = 0; i < 4; i++)
#pragma unroll
            for (int jj = 0; jj < 4; jj++) { ap[i][jj] = sB[jo + jj]; aq[i][jj] = 0.f; }
        for (int k4 = 0; k4 < 64; k4 += 4) {
            float a[4][4];
#pragma unroll
            for (int i = 0; i < 4; i++)
                *(float4*)a[i] = *(const float4*)(xs + (eo + i) * PADX + k4);
#pragma unroll
            for (int kk = 0; kk < 4; kk++) {
                float4 wb = *(const float4*)(sWb + (k4 + kk) * 64 + jo);
                float4 wc = *(const float4*)(sWc + (k4 + kk) * 64 + jo);
#pragma unroll
                for (int i = 0; i < 4; i++) {
                    float v = a[i][kk];
                    ap[i][0] = fmaf(v, wb.x, ap[i][0]); ap[i][1] = fmaf(v, wb.y, ap[i][1]);
                    ap[i][2] = fmaf(v, wb.z, ap[i][2]); ap[i][3] = fmaf(v, wb.w, ap[i][3]);
                    aq[i][0] = fmaf(v, wc.x, aq[i][0]); aq[i][1] = fmaf(v, wc.y, aq[i][1]);
                    aq[i][2] = fmaf(v, wc.z, aq[i][2]); aq[i][3] = fmaf(v, wc.w, aq[i][3]);
                }
            }
        }
#pragma unroll
        for (int i = 0; i < 4; i++) {
            int m = m0 + eo + i;
            if (m < NN) {
                *(float4*)(g_P + (size_t)m * 64 + jo) = make_float4(ap[i][0], ap[i][1], ap[i][2], ap[i][3]);
                *(float4*)(g_Q + (size_t)m * 64 + jo) = make_float4(aq[i][0], aq[i][1], aq[i][2], aq[i][3]);
            }
        }
        __syncthreads();
    }
}

// ---------------------------------------------------------------------------
// Edge layer 0: m0 = relu(h@F0 + P[src] + Q[dst]); store m0;
//               scatter Sh[dst]+=h, Sm0[dst]+=m0
// ---------------------------------------------------------------------------
__global__ __launch_bounds__(256) void k_edge0(
    const int* __restrict__ src, const int* __restrict__ dst)
{
    extern __shared__ float sm[];
    float* sF = sm;                      // 4096
    float* hb = sF + 4096;               // 64*PADX
    int* ssrc = (int*)(hb + 64 * PADX);  // 64
    int* sdst = ssrc + 64;               // 64
    for (int i = threadIdx.x; i < 4096; i += 256) sF[i] = g_F0[i];
    __syncthreads();
    const int jo = (threadIdx.x & 15) * 4;
    const int eo = (threadIdx.x >> 4) * 4;
    for (int t = blockIdx.x; t < NT64; t += gridDim.x) {
        const int e0 = t << 6;
        if (threadIdx.x < 64) {
            ssrc[threadIdx.x] = src[e0 + threadIdx.x];
            sdst[threadIdx.x] = dst[e0 + threadIdx.x];
        }
        for (int idx = threadIdx.x; idx < 1024; idx += 256) {
            int el = idx >> 4, j4 = (idx & 15) * 4;
            *(float4*)(hb + el * PADX + j4) =
                *(const float4*)(g_h + (size_t)(e0 + el) * 64 + j4);
        }
        __syncthreads();
        float acc[4][4];
#pragma unroll
        for (int i = 0; i < 4; i++)
#pragma unroll
            for (int jj = 0; jj < 4; jj++) acc[i][jj] = 0.f;
        for (int k4 = 0; k4 < 64; k4 += 4) {
            float a[4][4];
#pragma unroll
            for (int i = 0; i < 4; i++)
                *(float4*)a[i] = *(const float4*)(hb + (eo + i) * PADX + k4);
#pragma unroll
            for (int kk = 0; kk < 4; kk++) {
                float4 w = *(const float4*)(sF + (k4 + kk) * 64 + jo);
#pragma unroll
                for (int i = 0; i < 4; i++) {
                    acc[i][0] = fmaf(a[i][kk], w.x, acc[i][0]);
                    acc[i][1] = fmaf(a[i][kk], w.y, acc[i][1]);
                    acc[i][2] = fmaf(a[i][kk], w.z, acc[i][2]);
                    acc[i][3] = fmaf(a[i][kk], w.w, acc[i][3]);
                }
            }
        }
#pragma unroll
        for (int i = 0; i < 4; i++) {
            int sp = ssrc[eo + i], sd = sdst[eo + i];
            float4 p = *(const float4*)(g_P + (size_t)sp * 64 + jo);
            float4 q = *(const float4*)(g_Q + (size_t)sd * 64 + jo);
            float4 m0v = make_float4(
                fmaxf(acc[i][0] + p.x + q.x, 0.f),
                fmaxf(acc[i][1] + p.y + q.y, 0.f),
                fmaxf(acc[i][2] + p.z + q.z, 0.f),
                fmaxf(acc[i][3] + p.w + q.w, 0.f));
            *(float4*)(g_m0 + (size_t)(e0 + eo + i) * 64 + jo) = m0v;
            float4 hv = *(const float4*)(hb + (eo + i) * PADX + jo);
            red_add_v4(g_Sm0 + (size_t)sd * 64 + jo, m0v);
            red_add_v4(g_Sh  + (size_t)sd * 64 + jo, hv);
        }
        __syncthreads();
    }
}

// ---------------------------------------------------------------------------
// Edge layer 1: m1 = relu(h@G1 + m0@H1 + P[src] + Q[dst]); scatter Sm1[dst]+=m1
// ---------------------------------------------------------------------------
__global__ __launch_bounds__(256) void k_edge1(
    const int* __restrict__ src, const int* __restrict__ dst)
{
    extern __shared__ float sm[];
    float* sG = sm;                      // 4096
    float* sH = sG + 4096;               // 4096
    float* hb = sH + 4096;               // 64*PADX
    float* mb = hb + 64 * PADX;          // 64*PADX
    int* ssrc = (int*)(mb + 64 * PADX);  // 64
    int* sdst = ssrc + 64;               // 64
    for (int i = threadIdx.x; i < 4096; i += 256) { sG[i] = g_G1[i]; sH[i] = g_H1[i]; }
    __syncthreads();
    const int jo = (threadIdx.x & 15) * 4;
    const int eo = (threadIdx.x >> 4) * 4;
    for (int t = blockIdx.x; t < NT64; t += gridDim.x) {
        const int e0 = t << 6;
        if (threadIdx.x < 64) {
            ssrc[threadIdx.x] = src[e0 + threadIdx.x];
            sdst[threadIdx.x] = dst[e0 + threadIdx.x];
        }
        for (int idx = threadIdx.x; idx < 1024; idx += 256) {
            int el = idx >> 4, j4 = (idx & 15) * 4;
            *(float4*)(hb + el * PADX + j4) =
                *(const float4*)(g_h + (size_t)(e0 + el) * 64 + j4);
            *(float4*)(mb + el * PADX + j4) =
                *(const float4*)(g_m0 + (size_t)(e0 + el) * 64 + j4);
        }
        __syncthreads();
        float acc[4][4];
#pragma unroll
        for (int i = 0; i < 4; i++)
#pragma unroll
            for (int jj = 0; jj < 4; jj++) acc[i][jj] = 0.f;
        for (int k4 = 0; k4 < 64; k4 += 4) {
            float ah[4][4], am[4][4];
#pragma unroll
            for (int i = 0; i < 4; i++) {
                *(float4*)ah[i] = *(const float4*)(hb + (eo + i) * PADX + k4);
                *(float4*)am[i] = *(const float4*)(mb + (eo + i) * PADX + k4);
            }
#pragma unroll
            for (int kk = 0; kk < 4; kk++) {
                float4 wg = *(const float4*)(sG + (k4 + kk) * 64 + jo);
                float4 wh = *(const float4*)(sH + (k4 + kk) * 64 + jo);
#pragma unroll
                for (int i = 0; i < 4; i++) {
                    float vh = ah[i][kk], vm = am[i][kk];
                    acc[i][0] = fmaf(vh, wg.x, acc[i][0]); acc[i][1] = fmaf(vh, wg.y, acc[i][1]);
                    acc[i][2] = fmaf(vh, wg.z, acc[i][2]); acc[i][3] = fmaf(vh, wg.w, acc[i][3]);
                    acc[i][0] = fmaf(vm, wh.x, acc[i][0]); acc[i][1] = fmaf(vm, wh.y, acc[i][1]);
                    acc[i][2] = fmaf(vm, wh.z, acc[i][2]); acc[i][3] = fmaf(vm, wh.w, acc[i][3]);
                }
            }
        }
#pragma unroll
        for (int i = 0; i < 4; i++) {
            int sp = ssrc[eo + i], sd = sdst[eo + i];
            float4 p = *(const float4*)(g_P + (size_t)sp * 64 + jo);
            float4 q = *(const float4*)(g_Q + (size_t)sd * 64 + jo);
            float4 v = make_float4(
                fmaxf(acc[i][0] + p.x + q.x, 0.f),
                fmaxf(acc[i][1] + p.y + q.y, 0.f),
                fmaxf(acc[i][2] + p.z + q.z, 0.f),
                fmaxf(acc[i][3] + p.w + q.w, 0.f));
            red_add_v4(g_Sm1 + (size_t)sd * 64 + jo, v);
        }
        __syncthreads();
    }
}

// ---------------------------------------------------------------------------
// agg (layer0) = Sh@W2e + Sm0@W2_0 + deg*cr
// ---------------------------------------------------------------------------
__global__ __launch_bounds__(256) void k_agg0(
    const float* __restrict__ w2e, const float* __restrict__ w20)
{
    extern __shared__ float sm[];
    float* sWa = sm;
    float* sWb = sWa + 4096;
    float* sCr = sWb + 4096;            // 64
    float* sh  = sCr + 64;              // 64*PADX
    float* sm0 = sh + 64 * PADX;        // 64*PADX
    float* sdeg = sm0 + 64 * PADX;      // 64
    for (int i = threadIdx.x; i < 4096; i += 256) { sWa[i] = w2e[i]; sWb[i] = w20[i]; }
    if (threadIdx.x < 64) sCr[threadIdx.x] = g_cr[threadIdx.x];
    __syncthreads();
    const int jo = (threadIdx.x & 15) * 4;
    const int eo = (threadIdx.x >> 4) * 4;
    for (int t = blockIdx.x; t < NTN; t += gridDim.x) {
        const int m0 = t << 6;
        if (threadIdx.x < 64) {
            int m = m0 + threadIdx.x;
            sdeg[threadIdx.x] = (m < NN) ? g_deg[m] : 0.f;
        }
        for (int idx = threadIdx.x; idx < 1024; idx += 256) {
            int ml = idx >> 4, j4 = (idx & 15) * 4;
            int m = m0 + ml;
            float4 a = make_float4(0.f, 0.f, 0.f, 0.f), b = a;
            if (m < NN) {
                a = *(const float4*)(g_Sh + (size_t)m * 64 + j4);
                b = *(const float4*)(g_Sm0 + (size_t)m * 64 + j4);
            }
            *(float4*)(sh + ml * PADX + j4) = a;
            *(float4*)(sm0 + ml * PADX + j4) = b;
        }
        __syncthreads();
        float acc[4][4];
#pragma unroll
        for (int i = 0; i < 4; i++) {
            float d = sdeg[eo + i];
#pragma unroll
            for (int jj = 0; jj < 4; jj++) acc[i][jj] = d * sCr[jo + jj];
        }
        for (int k4 = 0; k4 < 64; k4 += 4) {
            float ah[4][4], am[4][4];
#pragma unroll
            for (int i = 0; i < 4; i++) {
                *(float4*)ah[i] = *(const float4*)(sh + (eo + i) * PADX + k4);
                *(float4*)am[i] = *(const float4*)(sm0 + (eo + i) * PADX + k4);
            }
#pragma unroll
            for (int kk = 0; kk < 4; kk++) {
                float4 wa = *(const float4*)(sWa + (k4 + kk) * 64 + jo);
                float4 wb = *(const float4*)(sWb + (k4 + kk) * 64 + jo);
#pragma unroll
                for (int i = 0; i < 4; i++) {
                    float vh = ah[i][kk], vm = am[i][kk];
                    acc[i][0] = fmaf(vh, wa.x, acc[i][0]); acc[i][1] = fmaf(vh, wa.y, acc[i][1]);
                    acc[i][2] = fmaf(vh, wa.z, acc[i][2]); acc[i][3] = fmaf(vh, wa.w, acc[i][3]);
                    acc[i][0] = fmaf(vm, wb.x, acc[i][0]); acc[i][1] = fmaf(vm, wb.y, acc[i][1]);
                    acc[i][2] = fmaf(vm, wb.z, acc[i][2]); acc[i][3] = fmaf(vm, wb.w, acc[i][3]);
                }
            }
        }
#pragma unroll
        for (int i = 0; i < 4; i++) {
            int m = m0 + eo + i;
            if (m < NN)
                *(float4*)(g_agg + (size_t)m * 64 + jo) =
                    make_float4(acc[i][0], acc[i][1], acc[i][2], acc[i][3]);
        }
        __syncthreads();
    }
}

// ---------------------------------------------------------------------------
// agg (layer1) += Sm1@W2_1 + deg*b2_1
// ---------------------------------------------------------------------------
__global__ __launch_bounds__(256) void k_agg1(
    const float* __restrict__ w21, const float* __restrict__ b21)
{
    extern __shared__ float sm[];
    float* sW = sm;                    // 4096
    float* sB = sW + 4096;             // 64
    float* sms = sB + 64;              // 64*PADX
    float* sdeg = sms + 64 * PADX;     // 64
    for (int i = threadIdx.x; i < 4096; i += 256) sW[i] = w21[i];
    if (threadIdx.x < 64) sB[threadIdx.x] = b21[threadIdx.x];
    __syncthreads();
    const int jo = (threadIdx.x & 15) * 4;
    const int eo = (threadIdx.x >> 4) * 4;
    for (int t = blockIdx.x; t < NTN; t += gridDim.x) {
        const int m0 = t << 6;
        if (threadIdx.x < 64) {
            int m = m0 + threadIdx.x;
            sdeg[threadIdx.x] = (m < NN) ? g_deg[m] : 0.f;
        }
        for (int idx = threadIdx.x; idx < 1024; idx += 256) {
            int ml = idx >> 4, j4 = (idx & 15) * 4;
            int m = m0 + ml;
            float4 v = (m < NN) ? *(const float4*)(g_Sm1 + (size_t)m * 64 + j4)
                                : make_float4(0.f, 0.f, 0.f, 0.f);
            *(float4*)(sms + ml * PADX + j4) = v;
        }
        __syncthreads();
        float acc[4][4];
#pragma unroll
        for (int i = 0; i < 4; i++) {
            float d = sdeg[eo + i];
#pragma unroll
            for (int jj = 0; jj < 4; jj++) acc[i][jj] = d * sB[jo + jj];
        }
        for (int k4 = 0; k4 < 64; k4 += 4) {
            float a[4][4];
#pragma unroll
            for (int i = 0; i < 4; i++)
                *(float4*)a[i] = *(const float4*)(sms + (eo + i) * PADX + k4);
#pragma unroll
            for (int kk = 0; kk < 4; kk++) {
                float4 w = *(const float4*)(sW + (k4 + kk) * 64 + jo);
#pragma unroll
                for (int i = 0; i < 4; i++) {
                    acc[i][0] = fmaf(a[i][kk], w.x, acc[i][0]);
                    acc[i][1] = fmaf(a[i][kk], w.y, acc[i][1]);
                    acc[i][2] = fmaf(a[i][kk], w.z, acc[i][2]);
                    acc[i][3] = fmaf(a[i][kk], w.w, acc[i][3]);
                }
            }
        }
#pragma unroll
        for (int i = 0; i < 4; i++) {
            int m = m0 + eo + i;
            if (m < NN) {
                float4 o = *(const float4*)(g_agg + (size_t)m * 64 + jo);
                *(float4*)(g_agg + (size_t)m * 64 + jo) = make_float4(
                    o.x + acc[i][0], o.y + acc[i][1], o.z + acc[i][2], o.w + acc[i][3]);
            }
        }
        __syncthreads();
    }
}

// ---------------------------------------------------------------------------
// Node step: x_h += relu(x_h@Wa + agg@Wb + b1)@W2 + b2
// ---------------------------------------------------------------------------
__global__ __launch_bounds__(256) void k_node(
    const float* __restrict__ wa, const float* __restrict__ wb,
    const float* __restrict__ b1, const float* __restrict__ w2,
    const float* __restrict__ b2)
{
    extern __shared__ float sm[];
    float* sWa = sm;
    float* sWb = sWa + 4096;
    float* sW2 = sWb + 4096;
    float* sB1 = sW2 + 4096;
    float* sB2 = sB1 + 64;
    float* xs  = sB2 + 64;
    float* as_ = xs + 64 * PADX;
    for (int i = threadIdx.x; i < 4096; i += 256) { sWa[i] = wa[i]; sWb[i] = wb[i]; sW2[i] = w2[i]; }
    if (threadIdx.x < 64) { sB1[threadIdx.x] = b1[threadIdx.x]; sB2[threadIdx.x] = b2[threadIdx.x]; }
    __syncthreads();
    const int jo = (threadIdx.x & 15) * 4;
    const int eo = (threadIdx.x >> 4) * 4;
    for (int t = blockIdx.x; t < NTN; t += gridDim.x) {
        const int m0 = t << 6;
        for (int idx = threadIdx.x; idx < 1024; idx += 256) {
            int ml = idx >> 4, j4 = (idx & 15) * 4;
            int m = m0 + ml;
            float4 vx = make_float4(0.f, 0.f, 0.f, 0.f), va = vx;
            if (m < NN) {
                vx = *(const float4*)(g_xh + (size_t)m * 64 + j4);
                va = *(const float4*)(g_agg + (size_t)m * 64 + j4);
            }
            *(float4*)(xs + ml * PADX + j4) = vx;
            *(float4*)(as_ + ml * PADX + j4) = va;
        }
        __syncthreads();
        float acc[4][4];
#pragma unroll
        for (int i = 0; i < 4; i++)
#pragma unroll
            for (int jj = 0; jj < 4; jj++) acc[i][jj] = sB1[jo + jj];
        for (int k4 = 0; k4 < 64; k4 += 4) {
            float ax[4][4], aa[4][4];
#pragma unroll
            for (int i = 0; i < 4; i++) {
                *(float4*)ax[i] = *(const float4*)(xs + (eo + i) * PADX + k4);
                *(float4*)aa[i] = *(const float4*)(as_ + (eo + i) * PADX + k4);
            }
#pragma unroll
            for (int kk = 0; kk < 4; kk++) {
                float4 wAv = *(const float4*)(sWa + (k4 + kk) * 64 + jo);
                float4 wBv = *(const float4*)(sWb + (k4 + kk) * 64 + jo);
#pragma unroll
                for (int i = 0; i < 4; i++) {
                    float vx = ax[i][kk], va = aa[i][kk];
                    acc[i][0] = fmaf(vx, wAv.x, acc[i][0]); acc[i][1] = fmaf(vx, wAv.y, acc[i][1]);
                    acc[i][2] = fmaf(vx, wAv.z, acc[i][2]); acc[i][3] = fmaf(vx, wAv.w, acc[i][3]);
                    acc[i][0] = fmaf(va, wBv.x, acc[i][0]); acc[i][1] = fmaf(va, wBv.y, acc[i][1]);
                    acc[i][2] = fmaf(va, wBv.z, acc[i][2]); acc[i][3] = fmaf(va, wBv.w, acc[i][3]);
                }
            }
        }
        __syncthreads();
#pragma unroll
        for (int i = 0; i < 4; i++)
            *(float4*)(as_ + (eo + i) * PADX + jo) = make_float4(
                fmaxf(acc[i][0], 0.f), fmaxf(acc[i][1], 0.f),
                fmaxf(acc[i][2], 0.f), fmaxf(acc[i][3], 0.f));
        __syncthreads();
        float acc2[4][4];
#pragma unroll
        for (int i = 0; i < 4; i++)
#pragma unroll
            for (int jj = 0; jj < 4; jj++) acc2[i][jj] = sB2[jo + jj];
        for (int k4 = 0; k4 < 64; k4 += 4) {
            float a[4][4];
#pragma unroll
            for (int i = 0; i < 4; i++)
                *(float4*)a[i] = *(const float4*)(as_ + (eo + i) * PADX + k4);
#pragma unroll
            for (int kk = 0; kk < 4; kk++) {
                float4 w = *(const float4*)(sW2 + (k4 + kk) * 64 + jo);
#pragma unroll
                for (int i = 0; i < 4; i++) {
                    acc2[i][0] = fmaf(a[i][kk], w.x, acc2[i][0]);
                    acc2[i][1] = fmaf(a[i][kk], w.y, acc2[i][1]);
                    acc2[i][2] = fmaf(a[i][kk], w.z, acc2[i][2]);
                    acc2[i][3] = fmaf(a[i][kk], w.w, acc2[i][3]);
                }
            }
        }
#pragma unroll
        for (int i = 0; i < 4; i++) {
            int m = m0 + eo + i;
            if (m < NN) {
                float4 r = *(const float4*)(xs + (eo + i) * PADX + jo);
                *(float4*)(g_xh + (size_t)m * 64 + jo) = make_float4(
                    r.x + acc2[i][0], r.y + acc2[i][1], r.z + acc2[i][2], r.w + acc2[i][3]);
            }
        }
        __syncthreads();
    }
}

// ---------------------------------------------------------------------------
// Decoder: out = relu(x_h@W1+b1)@W2 + b2  -> [N, 6]
// ---------------------------------------------------------------------------
__global__ __launch_bounds__(256) void k_decode(
    const float* __restrict__ w1, const float* __restrict__ b1,
    const float* __restrict__ w2, const float* __restrict__ b2,
    float* __restrict__ out)
{
    extern __shared__ float sm[];
    float* sW1  = sm;
    float* sW2p = sW1 + 4096;
    float* sB1  = sW2p + 512;
    float* sB2  = sB1 + 64;
    float* xs   = sB2 + 8;
    float* h1s  = xs + 64 * PADX;
    for (int i = threadIdx.x; i < 4096; i += 256) sW1[i] = w1[i];
    for (int i = threadIdx.x; i < 64 * 6; i += 256) sW2p[(i / 6) * 8 + (i % 6)] = w2[i];
    if (threadIdx.x < 64) sB1[threadIdx.x] = b1[threadIdx.x];
    if (threadIdx.x < 6) sB2[threadIdx.x] = b2[threadIdx.x];
    __syncthreads();
    const int jo = (threadIdx.x & 15) * 4;
    const int eo = (threadIdx.x >> 4) * 4;
    for (int t = blockIdx.x; t < NTN; t += gridDim.x) {
        const int m0 = t << 6;
        for (int idx = threadIdx.x; idx < 1024; idx += 256) {
            int ml = idx >> 4, j4 = (idx & 15) * 4;
            int m = m0 + ml;
            float4 v = (m < NN) ? *(const float4*)(g_xh + (size_t)m * 64 + j4)
                                : make_float4(0.f, 0.f, 0.f, 0.f);
            *(float4*)(xs + ml * PADX + j4) = v;
        }
        __syncthreads();
        float acc[4][4];
#pragma unroll
        for (int i = 0; i < 4; i++)
#pragma unroll
            for (int jj = 0; jj < 4; jj++) acc[i][jj] = sB1[jo + jj];
        for (int k4 = 0; k4 < 64; k4 += 4) {
            float a[4][4];
#pragma unroll
            for (int i = 0; i < 4; i++)
                *(float4*)a[i] = *(const float4*)(xs + (eo + i) * PADX + k4);
#pragma unroll
            for (int kk = 0; kk < 4; kk++) {
                float4 w = *(const float4*)(sW1 + (k4 + kk) * 64 + jo);
#pragma unroll
                for (int i = 0; i < 4; i++) {
                    acc[i][0] = fmaf(a[i][kk], w.x, acc[i][0]);
                    acc[i][1] = fmaf(a[i][kk], w.y, acc[i][1]);
                    acc[i][2] = fmaf(a[i][kk], w.z, acc[i][2]);
                    acc[i][3] = fmaf(a[i][kk], w.w, acc[i][3]);
                }
            }
        }
#pragma unroll
        for (int i = 0; i < 4; i++)
            *(float4*)(h1s + (eo + i) * PADX + jo) = make_float4(
                fmaxf(acc[i][0], 0.f), fmaxf(acc[i][1], 0.f),
                fmaxf(acc[i][2], 0.f), fmaxf(acc[i][3], 0.f));
        __syncthreads();
        for (int idx = threadIdx.x; idx < 64 * 6; idx += 256) {
            int nl = idx / 6, o = idx % 6;
            int m = m0 + nl;
            if (m < NN) {
                float s = sB2[o];
#pragma unroll 8
                for (int k = 0; k < 64; k++) s = fmaf(h1s[nl * PADX + k], sW2p[k * 8 + o], s);
                out[(size_t)m * 6 + o] = s;
            }
        }
        __syncthreads();
    }
}

// ---------------------------------------------------------------------------
extern "C" void kernel_launch(void* const* d_in, const int* in_sizes, int n_in,
                              void* d_out, int out_size)
{
    const float* x         = (const float*)d_in[0];
    const float* edge_attr = (const float*)d_in[1];
    const int*   ei        = (const int*)d_in[2];
    const float* enc_n_w1 = (const float*)d_in[3];
    const float* enc_n_b1 = (const float*)d_in[4];
    const float* enc_n_w2 = (const float*)d_in[5];
    const float* enc_n_b2 = (const float*)d_in[6];
    const float* enc_e_w1 = (const float*)d_in[7];
    const float* enc_e_b1 = (const float*)d_in[8];
    const float* enc_e_w2 = (const float*)d_in[9];
    const float* enc_e_b2 = (const float*)d_in[10];
    const float* pe_w1 = (const float*)d_in[11];
    const float* pe_b1 = (const float*)d_in[12];
    const float* pe_w2 = (const float*)d_in[13];
    const float* pe_b2 = (const float*)d_in[14];
    const float* pn_w1 = (const float*)d_in[15];
    const float* pn_b1 = (const float*)d_in[16];
    const float* pn_w2 = (const float*)d_in[17];
    const float* pn_b2 = (const float*)d_in[18];
    const float* dec_w1 = (const float*)d_in[19];
    const float* dec_b1 = (const float*)d_in[20];
    const float* dec_w2 = (const float*)d_in[21];
    const float* dec_b2 = (const float*)d_in[22];
    float* out = (float*)d_out;

    float *xh_p, *Sh_p, *Sm0_p, *Sm1_p, *deg_p, *c0_p, *c1_p;
    cudaGetSymbolAddress((void**)&xh_p,  g_xh);
    cudaGetSymbolAddress((void**)&Sh_p,  g_Sh);
    cudaGetSymbolAddress((void**)&Sm0_p, g_Sm0);
    cudaGetSymbolAddress((void**)&Sm1_p, g_Sm1);
    cudaGetSymbolAddress((void**)&deg_p, g_deg);
    cudaGetSymbolAddress((void**)&c0_p,  g_c0);
    cudaGetSymbolAddress((void**)&c1_p,  g_c1);

    const int SM_ENC_N = (4096 + 8 * 64 + 128 + 64 * 8 + 64 * PADX) * 4;
    const int SM_PQ    = (4096 * 2 + 64 + 64 * PADX) * 4;
    const int SM_E0    = (4096 + 64 * PADX + 128) * 4;
    const int SM_E1    = (4096 * 2 + 2 * 64 * PADX + 128) * 4;
    const int SM_A0    = (4096 * 2 + 64 + 2 * 64 * PADX + 64) * 4;
    const int SM_A1    = (4096 + 64 + 64 * PADX + 64) * 4;
    const int SM_NODE  = (4096 * 3 + 128 + 2 * 64 * PADX) * 4;
    const int SM_DEC   = (4096 + 512 + 72 + 2 * 64 * PADX) * 4;

    cudaFuncSetAttribute(k_encode<8>, cudaFuncAttributeMaxDynamicSharedMemorySize, SM_ENC_N);
    cudaFuncSetAttribute(k_pq,     cudaFuncAttributeMaxDynamicSharedMemorySize, SM_PQ);
    cudaFuncSetAttribute(k_edge0,  cudaFuncAttributeMaxDynamicSharedMemorySize, SM_E0);
    cudaFuncSetAttribute(k_edge1,  cudaFuncAttributeMaxDynamicSharedMemorySize, SM_E1);
    cudaFuncSetAttribute(k_agg0,   cudaFuncAttributeMaxDynamicSharedMemorySize, SM_A0);
    cudaFuncSetAttribute(k_agg1,   cudaFuncAttributeMaxDynamicSharedMemorySize, SM_A1);
    cudaFuncSetAttribute(k_node,   cudaFuncAttributeMaxDynamicSharedMemorySize, SM_NODE);
    cudaFuncSetAttribute(k_decode, cudaFuncAttributeMaxDynamicSharedMemorySize, SM_DEC);

    const int* src = ei;
    const int* dst = ei + EE;
    const size_t NB = (size_t)NN * 64 * sizeof(float);

    // zero accumulators
    cudaMemsetAsync(Sh_p,  0, NB, 0);
    cudaMemsetAsync(Sm0_p, 0, NB, 0);
    cudaMemsetAsync(Sm1_p, 0, NB, 0);
    cudaMemsetAsync(deg_p, 0, (size_t)NN * sizeof(float), 0);

    // encoders + precompute + degrees
    k_encode<8><<<782, 256, SM_ENC_N>>>(x, NN, enc_n_w1, enc_n_b1, enc_n_w2, enc_n_b2, xh_p);
    k_ench<<<888, 256>>>(edge_attr, enc_e_w1, enc_e_b1);
    k_prep<<<3, 256>>>(enc_e_w2, enc_e_b2, pe_w1, pe_b1, pe_w2, pe_b2);
    k_deg<<<592, 256>>>(dst);

    // layer 0
    k_pq<<<592, 256, SM_PQ>>>(pe_w1 + 64 * 64, pe_w1 + 128 * 64, c0_p);
    k_edge0<<<888, 256, SM_E0>>>(src, dst);
    k_agg0<<<592, 256, SM_A0>>>(enc_e_w2, pe_w2);
    k_node<<<296, 256, SM_NODE>>>(pn_w1, pn_w1 + 64 * 64,
                                  pn_b1, pn_w2, pn_b2);

    // layer 1
    k_pq<<<592, 256, SM_PQ>>>(pe_w1 + 192 * 64 + 64 * 64, pe_w1 + 192 * 64 + 128 * 64, c1_p);
    k_edge1<<<592, 256, SM_E1>>>(src, dst);
    k_agg1<<<592, 256, SM_A1>>>(pe_w2 + 4096, pe_b2 + 64);
    k_node<<<296, 256, SM_NODE>>>(pn_w1 + 128 * 64, pn_w1 + 128 * 64 + 64 * 64,
                                  pn_b1 + 64, pn_w2 + 4096, pn_b2 + 64);

    // decode
    k_decode<<<592, 256, SM_DEC>>>(dec_w1, dec_b1, dec_w2, dec_b2, out);
}

// round 11
// speedup vs baseline: 1.3378x; 1.3378x over previous
#include <cuda_runtime.h>

#define NN 50000
#define EE 800000
#define PADX 68   // 17 float4 per row: 16B-aligned rows, bank-shifted
#define NT64 (EE / 64)        // 12500 edge tiles
#define NTN ((NN + 63) >> 6)  // 782 node tiles

// persistent scratch (allocation-free rule: __device__ globals)
__device__ float g_xh[NN * 64];
__device__ float g_m0[EE * 64];   // layer-0 edge MLP hidden
__device__ float g_agg[NN * 64];
__device__ float g_P[NN * 64];
__device__ float g_Q[NN * 64];
__device__ float g_Sh [NN * 64];  // segment sums
__device__ float g_Sm0[NN * 64];
__device__ float g_Sm1[NN * 64];
__device__ float g_deg[NN];
__device__ float g_F0[4096];      // W2e @ W1a0
__device__ float g_G1[4096];      // W2e @ W1a1
__device__ float g_H1[4096];      // W2_0 @ W1a1
__device__ float g_c0[64];        // b1_0 + b2e@W1a0
__device__ float g_c1[64];        // b1_1 + (b2e+b2_0)@W1a1
__device__ float g_cr[64];        // b2e + b2_0

__device__ __forceinline__ void red_add_v4(float* p, float4 v) {
    asm volatile("red.global.add.v4.f32 [%0], {%1,%2,%3,%4};"
                 :: "l"(p), "f"(v.x), "f"(v.y), "f"(v.z), "f"(v.w) : "memory");
}

// ---------------------------------------------------------------------------
// Node encoder: x [N,8] -> relu(x@W1+b1)@W2+b2 -> x_h [N,64]
// ---------------------------------------------------------------------------
template <int FIN>
__global__ __launch_bounds__(256) void k_encode(
    const float* __restrict__ inp, int M,
    const float* __restrict__ w1, const float* __restrict__ b1,
    const float* __restrict__ w2, const float* __restrict__ b2,
    float* __restrict__ out)
{
    extern __shared__ float sm[];
    float* sW2 = sm;
    float* sW1 = sW2 + 4096;
    float* sB1 = sW1 + FIN * 64;
    float* sB2 = sB1 + 64;
    float* sIn = sB2 + 64;
    float* h1  = sIn + 64 * FIN;
    for (int i = threadIdx.x; i < 4096; i += 256) sW2[i] = w2[i];
    for (int i = threadIdx.x; i < FIN * 64; i += 256) sW1[i] = w1[i];
    if (threadIdx.x < 64) { sB1[threadIdx.x] = b1[threadIdx.x]; sB2[threadIdx.x] = b2[threadIdx.x]; }
    __syncthreads();
    const int jo = (threadIdx.x & 15) * 4;
    const int eo = (threadIdx.x >> 4) * 4;
    const int ntiles = (M + 63) >> 6;
    for (int t = blockIdx.x; t < ntiles; t += gridDim.x) {
        const int m0 = t << 6;
        for (int idx = threadIdx.x; idx < 64 * FIN; idx += 256) {
            int m = m0 + idx / FIN;
            sIn[idx] = (m < M) ? inp[(size_t)m0 * FIN + idx] : 0.f;
        }
        __syncthreads();
        for (int idx = threadIdx.x; idx < 4096; idx += 256) {
            int ml = idx >> 6, j = idx & 63;
            float acc = sB1[j];
#pragma unroll
            for (int k = 0; k < FIN; k++) acc = fmaf(sIn[ml * FIN + k], sW1[k * 64 + j], acc);
            h1[ml * PADX + j] = fmaxf(acc, 0.f);
        }
        __syncthreads();
        float acc[4][4];
#pragma unroll
        for (int i = 0; i < 4; i++)
#pragma unroll
            for (int jj = 0; jj < 4; jj++) acc[i][jj] = sB2[jo + jj];
        for (int k4 = 0; k4 < 64; k4 += 4) {
            float a[4][4];
#pragma unroll
            for (int i = 0; i < 4; i++)
                *(float4*)a[i] = *(const float4*)(h1 + (eo + i) * PADX + k4);
#pragma unroll
            for (int kk = 0; kk < 4; kk++) {
                float4 w = *(const float4*)(sW2 + (k4 + kk) * 64 + jo);
#pragma unroll
                for (int i = 0; i < 4; i++) {
                    acc[i][0] = fmaf(a[i][kk], w.x, acc[i][0]);
                    acc[i][1] = fmaf(a[i][kk], w.y, acc[i][1]);
                    acc[i][2] = fmaf(a[i][kk], w.z, acc[i][2]);
                    acc[i][3] = fmaf(a[i][kk], w.w, acc[i][3]);
                }
            }
        }
#pragma unroll
        for (int i = 0; i < 4; i++) {
            int m = m0 + eo + i;
            if (m < M)
                *(float4*)(out + (size_t)m * 64 + jo) = make_float4(acc[i][0], acc[i][1], acc[i][2], acc[i][3]);
        }
        __syncthreads();
    }
}

// ---------------------------------------------------------------------------
// Precompute fused weights/biases (3 blocks).
//  b0: F0 = w2e@W1a0, c0, cr ; b1: G1 = w2e@W1a1, c1 ; b2: H1 = W2_0@W1a1
// ---------------------------------------------------------------------------
__global__ __launch_bounds__(256) void k_prep(
    const float* __restrict__ w2e, const float* __restrict__ b2e,
    const float* __restrict__ pe_w1, const float* __restrict__ pe_b1,
    const float* __restrict__ pe_w2, const float* __restrict__ pe_b2)
{
    __shared__ float sA[4096], sB[4096];
    const float* w1a0 = pe_w1;               // layer0 rows [0,64)
    const float* w1a1 = pe_w1 + 192 * 64;    // layer1 rows [0,64)
    const float *A, *B; float* O;
    if (blockIdx.x == 0)      { A = w2e;   B = w1a0; O = g_F0; }
    else if (blockIdx.x == 1) { A = w2e;   B = w1a1; O = g_G1; }
    else                      { A = pe_w2; B = w1a1; O = g_H1; }
    for (int i = threadIdx.x; i < 4096; i += 256) { sA[i] = A[i]; sB[i] = B[i]; }
    __syncthreads();
    for (int idx = threadIdx.x; idx < 4096; idx += 256) {
        int k = idx >> 6, j = idx & 63;
        float acc = 0.f;
#pragma unroll 8
        for (int t = 0; t < 64; t++) acc = fmaf(sA[k * 64 + t], sB[t * 64 + j], acc);
        O[idx] = acc;
    }
    if (blockIdx.x == 0 && threadIdx.x < 64) {
        int j = threadIdx.x;
        float a = pe_b1[j];
        for (int t = 0; t < 64; t++) a = fmaf(b2e[t], sB[t * 64 + j], a);
        g_c0[j] = a;
        g_cr[j] = b2e[j] + pe_b2[j];
    }
    if (blockIdx.x == 1 && threadIdx.x < 64) {
        int j = threadIdx.x;
        float a = pe_b1[64 + j];
        for (int t = 0; t < 64; t++) a = fmaf(b2e[t] + pe_b2[t], sB[t * 64 + j], a);
        g_c1[j] = a;
    }
}

// degree: deg[v] = #edges with dst==v
__global__ __launch_bounds__(256) void k_deg(const int* __restrict__ dst) {
    for (int e = blockIdx.x * 256 + threadIdx.x; e < EE; e += gridDim.x * 256)
        atomicAdd(g_deg + dst[e], 1.0f);
}

// ---------------------------------------------------------------------------
// P = x_h @ W1b + c ; Q = x_h @ W1c    (c = fused bias, device pointer)
// ---------------------------------------------------------------------------
__global__ __launch_bounds__(256) void k_pq(
    const float* __restrict__ w1b, const float* __restrict__ w1c,
    const float* __restrict__ b1)
{
    extern __shared__ float sm[];
    float* sWb = sm;
    float* sWc = sWb + 4096;
    float* sB  = sWc + 4096;
    float* xs  = sB + 64;
    for (int i = threadIdx.x; i < 4096; i += 256) { sWb[i] = w1b[i]; sWc[i] = w1c[i]; }
    if (threadIdx.x < 64) sB[threadIdx.x] = b1[threadIdx.x];
    __syncthreads();
    const int jo = (threadIdx.x & 15) * 4;
    const int eo = (threadIdx.x >> 4) * 4;
    for (int t = blockIdx.x; t < NTN; t += gridDim.x) {
        const int m0 = t << 6;
        for (int idx = threadIdx.x; idx < 1024; idx += 256) {
            int ml = idx >> 4, j4 = (idx & 15) * 4;
            int m = m0 + ml;
            float4 v = (m < NN) ? *(const float4*)(g_xh + (size_t)m * 64 + j4)
                                : make_float4(0.f, 0.f, 0.f, 0.f);
            *(float4*)(xs + ml * PADX + j4) = v;
        }
        __syncthreads();
        float ap[4][4], aq[4][4];
#pragma unroll
        for (int i = 0; i < 4; i++)
#pragma unroll
            for (int jj = 0; jj < 4; jj++) { ap[i][jj] = sB[jo + jj]; aq[i][jj] = 0.f; }
        for (int k4 = 0; k4 < 64; k4 += 4) {
            float a[4][4];
#pragma unroll
            for (int i = 0; i < 4; i++)
                *(float4*)a[i] = *(const float4*)(xs + (eo + i) * PADX + k4);
#pragma unroll
            for (int kk = 0; kk < 4; kk++) {
                float4 wb = *(const float4*)(sWb + (k4 + kk) * 64 + jo);
                float4 wc = *(const float4*)(sWc + (k4 + kk) * 64 + jo);
#pragma unroll
                for (int i = 0; i < 4; i++) {
                    float v = a[i][kk];
                    ap[i][0] = fmaf(v, wb.x, ap[i][0]); ap[i][1] = fmaf(v, wb.y, ap[i][1]);
                    ap[i][2] = fmaf(v, wb.z, ap[i][2]); ap[i][3] = fmaf(v, wb.w, ap[i][3]);
                    aq[i][0] = fmaf(v, wc.x, aq[i][0]); aq[i][1] = fmaf(v, wc.y, aq[i][1]);
                    aq[i][2] = fmaf(v, wc.z, aq[i][2]); aq[i][3] = fmaf(v, wc.w, aq[i][3]);
                }
            }
        }
#pragma unroll
        for (int i = 0; i < 4; i++) {
            int m = m0 + eo + i;
            if (m < NN) {
                *(float4*)(g_P + (size_t)m * 64 + jo) = make_float4(ap[i][0], ap[i][1], ap[i][2], ap[i][3]);
                *(float4*)(g_Q + (size_t)m * 64 + jo) = make_float4(aq[i][0], aq[i][1], aq[i][2], aq[i][3]);
            }
        }
        __syncthreads();
    }
}

// ---------------------------------------------------------------------------
// Edge layer 0 (h fused): h = relu(ea@W1e+b1e) in smem;
//   m0 = relu(h@F0 + P[src] + Q[dst]); store m0; scatter Sh+=h, Sm0+=m0
// ---------------------------------------------------------------------------
__global__ __launch_bounds__(256) void k_edge0(
    const int* __restrict__ src, const int* __restrict__ dst,
    const float* __restrict__ ea,
    const float* __restrict__ w1e, const float* __restrict__ b1e)
{
    extern __shared__ float sm[];
    float* sF  = sm;                      // 4096
    float* sW1 = sF + 4096;               // 256
    float* sB1 = sW1 + 256;               // 64
    float* sIn = sB1 + 64;                // 256
    float* hb  = sIn + 256;               // 64*PADX
    int* ssrc = (int*)(hb + 64 * PADX);   // 64
    int* sdst = ssrc + 64;                // 64
    for (int i = threadIdx.x; i < 4096; i += 256) sF[i] = g_F0[i];
    if (threadIdx.x < 256) sW1[threadIdx.x] = w1e[threadIdx.x];
    if (threadIdx.x < 64) sB1[threadIdx.x] = b1e[threadIdx.x];
    __syncthreads();
    const int jo = (threadIdx.x & 15) * 4;
    const int eo = (threadIdx.x >> 4) * 4;
    for (int t = blockIdx.x; t < NT64; t += gridDim.x) {
        const int e0 = t << 6;
        if (threadIdx.x < 64) {
            ssrc[threadIdx.x] = src[e0 + threadIdx.x];
            sdst[threadIdx.x] = dst[e0 + threadIdx.x];
        }
        sIn[threadIdx.x] = ea[(size_t)e0 * 4 + threadIdx.x];
        __syncthreads();
        // h = relu(ea@W1e + b1e) into shared
        for (int idx = threadIdx.x; idx < 4096; idx += 256) {
            int ml = idx >> 6, j = idx & 63;
            float acc = sB1[j];
#pragma unroll
            for (int k = 0; k < 4; k++) acc = fmaf(sIn[ml * 4 + k], sW1[k * 64 + j], acc);
            hb[ml * PADX + j] = fmaxf(acc, 0.f);
        }
        __syncthreads();
        float acc[4][4];
#pragma unroll
        for (int i = 0; i < 4; i++)
#pragma unroll
            for (int jj = 0; jj < 4; jj++) acc[i][jj] = 0.f;
        for (int k4 = 0; k4 < 64; k4 += 4) {
            float a[4][4];
#pragma unroll
            for (int i = 0; i < 4; i++)
                *(float4*)a[i] = *(const float4*)(hb + (eo + i) * PADX + k4);
#pragma unroll
            for (int kk = 0; kk < 4; kk++) {
                float4 w = *(const float4*)(sF + (k4 + kk) * 64 + jo);
#pragma unroll
                for (int i = 0; i < 4; i++) {
                    acc[i][0] = fmaf(a[i][kk], w.x, acc[i][0]);
                    acc[i][1] = fmaf(a[i][kk], w.y, acc[i][1]);
                    acc[i][2] = fmaf(a[i][kk], w.z, acc[i][2]);
                    acc[i][3] = fmaf(a[i][kk], w.w, acc[i][3]);
                }
            }
        }
#pragma unroll
        for (int i = 0; i < 4; i++) {
            int sp = ssrc[eo + i], sd = sdst[eo + i];
            float4 p = *(const float4*)(g_P + (size_t)sp * 64 + jo);
            float4 q = *(const float4*)(g_Q + (size_t)sd * 64 + jo);
            float4 m0v = make_float4(
                fmaxf(acc[i][0] + p.x + q.x, 0.f),
                fmaxf(acc[i][1] + p.y + q.y, 0.f),
                fmaxf(acc[i][2] + p.z + q.z, 0.f),
                fmaxf(acc[i][3] + p.w + q.w, 0.f));
            *(float4*)(g_m0 + (size_t)(e0 + eo + i) * 64 + jo) = m0v;
            float4 hv = *(const float4*)(hb + (eo + i) * PADX + jo);
            red_add_v4(g_Sm0 + (size_t)sd * 64 + jo, m0v);
            red_add_v4(g_Sh  + (size_t)sd * 64 + jo, hv);
        }
        __syncthreads();
    }
}

// ---------------------------------------------------------------------------
// Edge layer 1 (h fused): m1 = relu(h@G1 + m0@H1 + P[src] + Q[dst]);
//                         scatter Sm1[dst]+=m1
// ---------------------------------------------------------------------------
__global__ __launch_bounds__(256) void k_edge1(
    const int* __restrict__ src, const int* __restrict__ dst,
    const float* __restrict__ ea,
    const float* __restrict__ w1e, const float* __restrict__ b1e)
{
    extern __shared__ float sm[];
    float* sG  = sm;                      // 4096
    float* sH  = sG + 4096;               // 4096
    float* sW1 = sH + 4096;               // 256
    float* sB1 = sW1 + 256;               // 64
    float* sIn = sB1 + 64;                // 256
    float* hb  = sIn + 256;               // 64*PADX
    float* mb  = hb + 64 * PADX;          // 64*PADX
    int* ssrc = (int*)(mb + 64 * PADX);   // 64
    int* sdst = ssrc + 64;                // 64
    for (int i = threadIdx.x; i < 4096; i += 256) { sG[i] = g_G1[i]; sH[i] = g_H1[i]; }
    if (threadIdx.x < 256) sW1[threadIdx.x] = w1e[threadIdx.x];
    if (threadIdx.x < 64) sB1[threadIdx.x] = b1e[threadIdx.x];
    __syncthreads();
    const int jo = (threadIdx.x & 15) * 4;
    const int eo = (threadIdx.x >> 4) * 4;
    for (int t = blockIdx.x; t < NT64; t += gridDim.x) {
        const int e0 = t << 6;
        if (threadIdx.x < 64) {
            ssrc[threadIdx.x] = src[e0 + threadIdx.x];
            sdst[threadIdx.x] = dst[e0 + threadIdx.x];
        }
        sIn[threadIdx.x] = ea[(size_t)e0 * 4 + threadIdx.x];
        for (int idx = threadIdx.x; idx < 1024; idx += 256) {
            int el = idx >> 4, j4 = (idx & 15) * 4;
            *(float4*)(mb + el * PADX + j4) =
                *(const float4*)(g_m0 + (size_t)(e0 + el) * 64 + j4);
        }
        __syncthreads();
        // h = relu(ea@W1e + b1e) into shared
        for (int idx = threadIdx.x; idx < 4096; idx += 256) {
            int ml = idx >> 6, j = idx & 63;
            float acc = sB1[j];
#pragma unroll
            for (int k = 0; k < 4; k++) acc = fmaf(sIn[ml * 4 + k], sW1[k * 64 + j], acc);
            hb[ml * PADX + j] = fmaxf(acc, 0.f);
        }
        __syncthreads();
        float acc[4][4];
#pragma unroll
        for (int i = 0; i < 4; i++)
#pragma unroll
            for (int jj = 0; jj < 4; jj++) acc[i][jj] = 0.f;
        for (int k4 = 0; k4 < 64; k4 += 4) {
            float ah[4][4], am[4][4];
#pragma unroll
            for (int i = 0; i < 4; i++) {
                *(float4*)ah[i] = *(const float4*)(hb + (eo + i) * PADX + k4);
                *(float4*)am[i] = *(const float4*)(mb + (eo + i) * PADX + k4);
            }
#pragma unroll
            for (int kk = 0; kk < 4; kk++) {
                float4 wg = *(const float4*)(sG + (k4 + kk) * 64 + jo);
                float4 wh = *(const float4*)(sH + (k4 + kk) * 64 + jo);
#pragma unroll
                for (int i = 0; i < 4; i++) {
                    float vh = ah[i][kk], vm = am[i][kk];
                    acc[i][0] = fmaf(vh, wg.x, acc[i][0]); acc[i][1] = fmaf(vh, wg.y, acc[i][1]);
                    acc[i][2] = fmaf(vh, wg.z, acc[i][2]); acc[i][3] = fmaf(vh, wg.w, acc[i][3]);
                    acc[i][0] = fmaf(vm, wh.x, acc[i][0]); acc[i][1] = fmaf(vm, wh.y, acc[i][1]);
                    acc[i][2] = fmaf(vm, wh.z, acc[i][2]); acc[i][3] = fmaf(vm, wh.w, acc[i][3]);
                }
            }
        }
#pragma unroll
        for (int i = 0; i < 4; i++) {
            int sp = ssrc[eo + i], sd = sdst[eo + i];
            float4 p = *(const float4*)(g_P + (size_t)sp * 64 + jo);
            float4 q = *(const float4*)(g_Q + (size_t)sd * 64 + jo);
            float4 v = make_float4(
                fmaxf(acc[i][0] + p.x + q.x, 0.f),
                fmaxf(acc[i][1] + p.y + q.y, 0.f),
                fmaxf(acc[i][2] + p.z + q.z, 0.f),
                fmaxf(acc[i][3] + p.w + q.w, 0.f));
            red_add_v4(g_Sm1 + (size_t)sd * 64 + jo, v);
        }
        __syncthreads();
    }
}

// ---------------------------------------------------------------------------
// agg (layer0) = Sh@W2e + Sm0@W2_0 + deg*cr
// ---------------------------------------------------------------------------
__global__ __launch_bounds__(256) void k_agg0(
    const float* __restrict__ w2e, const float* __restrict__ w20)
{
    extern __shared__ float sm[];
    float* sWa = sm;
    float* sWb = sWa + 4096;
    float* sCr = sWb + 4096;            // 64
    float* sh  = sCr + 64;              // 64*PADX
    float* sm0 = sh + 64 * PADX;        // 64*PADX
    float* sdeg = sm0 + 64 * PADX;      // 64
    for (int i = threadIdx.x; i < 4096; i += 256) { sWa[i] = w2e[i]; sWb[i] = w20[i]; }
    if (threadIdx.x < 64) sCr[threadIdx.x] = g_cr[threadIdx.x];
    __syncthreads();
    const int jo = (threadIdx.x & 15) * 4;
    const int eo = (threadIdx.x >> 4) * 4;
    for (int t = blockIdx.x; t < NTN; t += gridDim.x) {
        const int m0 = t << 6;
        if (threadIdx.x < 64) {
            int m = m0 + threadIdx.x;
            sdeg[threadIdx.x] = (m < NN) ? g_deg[m] : 0.f;
        }
        for (int idx = threadIdx.x; idx < 1024; idx += 256) {
            int ml = idx >> 4, j4 = (idx & 15) * 4;
            int m = m0 + ml;
            float4 a = make_float4(0.f, 0.f, 0.f, 0.f), b = a;
            if (m < NN) {
                a = *(const float4*)(g_Sh + (size_t)m * 64 + j4);
                b = *(const float4*)(g_Sm0 + (size_t)m * 64 + j4);
            }
            *(float4*)(sh + ml * PADX + j4) = a;
            *(float4*)(sm0 + ml * PADX + j4) = b;
        }
        __syncthreads();
        float acc[4][4];
#pragma unroll
        for (int i = 0; i < 4; i++) {
            float d = sdeg[eo + i];
#pragma unroll
            for (int jj = 0; jj < 4; jj++) acc[i][jj] = d * sCr[jo + jj];
        }
        for (int k4 = 0; k4 < 64; k4 += 4) {
            float ah[4][4], am[4][4];
#pragma unroll
            for (int i = 0; i < 4; i++) {
                *(float4*)ah[i] = *(const float4*)(sh + (eo + i) * PADX + k4);
                *(float4*)am[i] = *(const float4*)(sm0 + (eo + i) * PADX + k4);
            }
#pragma unroll
            for (int kk = 0; kk < 4; kk++) {
                float4 wa = *(const float4*)(sWa + (k4 + kk) * 64 + jo);
                float4 wb = *(const float4*)(sWb + (k4 + kk) * 64 + jo);
#pragma unroll
                for (int i = 0; i < 4; i++) {
                    float vh = ah[i][kk], vm = am[i][kk];
                    acc[i][0] = fmaf(vh, wa.x, acc[i][0]); acc[i][1] = fmaf(vh, wa.y, acc[i][1]);
                    acc[i][2] = fmaf(vh, wa.z, acc[i][2]); acc[i][3] = fmaf(vh, wa.w, acc[i][3]);
                    acc[i][0] = fmaf(vm, wb.x, acc[i][0]); acc[i][1] = fmaf(vm, wb.y, acc[i][1]);
                    acc[i][2] = fmaf(vm, wb.z, acc[i][2]); acc[i][3] = fmaf(vm, wb.w, acc[i][3]);
                }
            }
        }
#pragma unroll
        for (int i = 0; i < 4; i++) {
            int m = m0 + eo + i;
            if (m < NN)
                *(float4*)(g_agg + (size_t)m * 64 + jo) =
                    make_float4(acc[i][0], acc[i][1], acc[i][2], acc[i][3]);
        }
        __syncthreads();
    }
}

// ---------------------------------------------------------------------------
// agg (layer1) += Sm1@W2_1 + deg*b2_1
// ---------------------------------------------------------------------------
__global__ __launch_bounds__(256) void k_agg1(
    const float* __restrict__ w21, const float* __restrict__ b21)
{
    extern __shared__ float sm[];
    float* sW = sm;                    // 4096
    float* sB = sW + 4096;             // 64
    float* sms = sB + 64;              // 64*PADX
    float* sdeg = sms + 64 * PADX;     // 64
    for (int i = threadIdx.x; i < 4096; i += 256) sW[i] = w21[i];
    if (threadIdx.x < 64) sB[threadIdx.x] = b21[threadIdx.x];
    __syncthreads();
    const int jo = (threadIdx.x & 15) * 4;
    const int eo = (threadIdx.x >> 4) * 4;
    for (int t = blockIdx.x; t < NTN; t += gridDim.x) {
        const int m0 = t << 6;
        if (threadIdx.x < 64) {
            int m = m0 + threadIdx.x;
            sdeg[threadIdx.x] = (m < NN) ? g_deg[m] : 0.f;
        }
        for (int idx = threadIdx.x; idx < 1024; idx += 256) {
            int ml = idx >> 4, j4 = (idx & 15) * 4;
            int m = m0 + ml;
            float4 v = (m < NN) ? *(const float4*)(g_Sm1 + (size_t)m * 64 + j4)
                                : make_float4(0.f, 0.f, 0.f, 0.f);
            *(float4*)(sms + ml * PADX + j4) = v;
        }
        __syncthreads();
        float acc[4][4];
#pragma unroll
        for (int i = 0; i < 4; i++) {
            float d = sdeg[eo + i];
#pragma unroll
            for (int jj = 0; jj < 4; jj++) acc[i][jj] = d * sB[jo + jj];
        }
        for (int k4 = 0; k4 < 64; k4 += 4) {
            float a[4][4];
#pragma unroll
            for (int i = 0; i < 4; i++)
                *(float4*)a[i] = *(const float4*)(sms + (eo + i) * PADX + k4);
#pragma unroll
            for (int kk = 0; kk < 4; kk++) {
                float4 w = *(const float4*)(sW + (k4 + kk) * 64 + jo);
#pragma unroll
                for (int i = 0; i < 4; i++) {
                    acc[i][0] = fmaf(a[i][kk], w.x, acc[i][0]);
                    acc[i][1] = fmaf(a[i][kk], w.y, acc[i][1]);
                    acc[i][2] = fmaf(a[i][kk], w.z, acc[i][2]);
                    acc[i][3] = fmaf(a[i][kk], w.w, acc[i][3]);
                }
            }
        }
#pragma unroll
        for (int i = 0; i < 4; i++) {
            int m = m0 + eo + i;
            if (m < NN) {
                float4 o = *(const float4*)(g_agg + (size_t)m * 64 + jo);
                *(float4*)(g_agg + (size_t)m * 64 + jo) = make_float4(
                    o.x + acc[i][0], o.y + acc[i][1], o.z + acc[i][2], o.w + acc[i][3]);
            }
        }
        __syncthreads();
    }
}

// ---------------------------------------------------------------------------
// Node step: x_h += relu(x_h@Wa + agg@Wb + b1)@W2 + b2
// ---------------------------------------------------------------------------
__global__ __launch_bounds__(256) void k_node(
    const float* __restrict__ wa, const float* __restrict__ wb,
    const float* __restrict__ b1, const float* __restrict__ w2,
    const float* __restrict__ b2)
{
    extern __shared__ float sm[];
    float* sWa = sm;
    float* sWb = sWa + 4096;
    float* sW2 = sWb + 4096;
    float* sB1 = sW2 + 4096;
    float* sB2 = sB1 + 64;
    float* xs  = sB2 + 64;
    float* as_ = xs + 64 * PADX;
    for (int i = threadIdx.x; i < 4096; i += 256) { sWa[i] = wa[i]; sWb[i] = wb[i]; sW2[i] = w2[i]; }
    if (threadIdx.x < 64) { sB1[threadIdx.x] = b1[threadIdx.x]; sB2[threadIdx.x] = b2[threadIdx.x]; }
    __syncthreads();
    const int jo = (threadIdx.x & 15) * 4;
    const int eo = (threadIdx.x >> 4) * 4;
    for (int t = blockIdx.x; t < NTN; t += gridDim.x) {
        const int m0 = t << 6;
        for (int idx = threadIdx.x; idx < 1024; idx += 256) {
            int ml = idx >> 4, j4 = (idx & 15) * 4;
            int m = m0 + ml;
            float4 vx = make_float4(0.f, 0.f, 0.f, 0.f), va = vx;
            if (m < NN) {
                vx = *(const float4*)(g_xh + (size_t)m * 64 + j4);
                va = *(const float4*)(g_agg + (size_t)m * 64 + j4);
            }
            *(float4*)(xs + ml * PADX + j4) = vx;
            *(float4*)(as_ + ml * PADX + j4) = va;
        }
        __syncthreads();
        float acc[4][4];
#pragma unroll
        for (int i = 0; i < 4; i++)
#pragma unroll
            for (int jj = 0; jj < 4; jj++) acc[i][jj] = sB1[jo + jj];
        for (int k4 = 0; k4 < 64; k4 += 4) {
            float ax[4][4], aa[4][4];
#pragma unroll
            for (int i = 0; i < 4; i++) {
                *(float4*)ax[i] = *(const float4*)(xs + (eo + i) * PADX + k4);
                *(float4*)aa[i] = *(const float4*)(as_ + (eo + i) * PADX + k4);
            }
#pragma unroll
            for (int kk = 0; kk < 4; kk++) {
                float4 wAv = *(const float4*)(sWa + (k4 + kk) * 64 + jo);
                float4 wBv = *(const float4*)(sWb + (k4 + kk) * 64 + jo);
#pragma unroll
                for (int i = 0; i < 4; i++) {
                    float vx = ax[i][kk], va = aa[i][kk];
                    acc[i][0] = fmaf(vx, wAv.x, acc[i][0]); acc[i][1] = fmaf(vx, wAv.y, acc[i][1]);
                    acc[i][2] = fmaf(vx, wAv.z, acc[i][2]); acc[i][3] = fmaf(vx, wAv.w, acc[i][3]);
                    acc[i][0] = fmaf(va, wBv.x, acc[i][0]); acc[i][1] = fmaf(va, wBv.y, acc[i][1]);
                    acc[i][2] = fmaf(va, wBv.z, acc[i][2]); acc[i][3] = fmaf(va, wBv.w, acc[i][3]);
                }
            }
        }
        __syncthreads();
#pragma unroll
        for (int i = 0; i < 4; i++)
            *(float4*)(as_ + (eo + i) * PADX + jo) = make_float4(
                fmaxf(acc[i][0], 0.f), fmaxf(acc[i][1], 0.f),
                fmaxf(acc[i][2], 0.f), fmaxf(acc[i][3], 0.f));
        __syncthreads();
        float acc2[4][4];
#pragma unroll
        for (int i = 0; i < 4; i++)
#pragma unroll
            for (int jj = 0; jj < 4; jj++) acc2[i][jj] = sB2[jo + jj];
        for (int k4 = 0; k4 < 64; k4 += 4) {
            float a[4][4];
#pragma unroll
            for (int i = 0; i < 4; i++)
                *(float4*)a[i] = *(const float4*)(as_ + (eo + i) * PADX + k4);
#pragma unroll
            for (int kk = 0; kk < 4; kk++) {
                float4 w = *(const float4*)(sW2 + (k4 + kk) * 64 + jo);
#pragma unroll
                for (int i = 0; i < 4; i++) {
                    acc2[i][0] = fmaf(a[i][kk], w.x, acc2[i][0]);
                    acc2[i][1] = fmaf(a[i][kk], w.y, acc2[i][1]);
                    acc2[i][2] = fmaf(a[i][kk], w.z, acc2[i][2]);
                    acc2[i][3] = fmaf(a[i][kk], w.w, acc2[i][3]);
                }
            }
        }
#pragma unroll
        for (int i = 0; i < 4; i++) {
            int m = m0 + eo + i;
            if (m < NN) {
                float4 r = *(const float4*)(xs + (eo + i) * PADX + jo);
                *(float4*)(g_xh + (size_t)m * 64 + jo) = make_float4(
                    r.x + acc2[i][0], r.y + acc2[i][1], r.z + acc2[i][2], r.w + acc2[i][3]);
            }
        }
        __syncthreads();
    }
}

// ---------------------------------------------------------------------------
// Decoder: out = relu(x_h@W1+b1)@W2 + b2  -> [N, 6]
// ---------------------------------------------------------------------------
__global__ __launch_bounds__(256) void k_decode(
    const float* __restrict__ w1, const float* __restrict__ b1,
    const float* __restrict__ w2, const float* __restrict__ b2,
    float* __restrict__ out)
{
    extern __shared__ float sm[];
    float* sW1  = sm;
    float* sW2p = sW1 + 4096;
    float* sB1  = sW2p + 512;
    float* sB2  = sB1 + 64;
    float* xs   = sB2 + 8;
    float* h1s  = xs + 64 * PADX;
    for (int i = threadIdx.x; i < 4096; i += 256) sW1[i] = w1[i];
    for (int i = threadIdx.x; i < 64 * 6; i += 256) sW2p[(i / 6) * 8 + (i % 6)] = w2[i];
    if (threadIdx.x < 64) sB1[threadIdx.x] = b1[threadIdx.x];
    if (threadIdx.x < 6) sB2[threadIdx.x] = b2[threadIdx.x];
    __syncthreads();
    const int jo = (threadIdx.x & 15) * 4;
    const int eo = (threadIdx.x >> 4) * 4;
    for (int t = blockIdx.x; t < NTN; t += gridDim.x) {
        const int m0 = t << 6;
        for (int idx = threadIdx.x; idx < 1024; idx += 256) {
            int ml = idx >> 4, j4 = (idx & 15) * 4;
            int m = m0 + ml;
            float4 v = (m < NN) ? *(const float4*)(g_xh + (size_t)m * 64 + j4)
                                : make_float4(0.f, 0.f, 0.f, 0.f);
            *(float4*)(xs + ml * PADX + j4) = v;
        }
        __syncthreads();
        float acc[4][4];
#pragma unroll
        for (int i = 0; i < 4; i++)
#pragma unroll
            for (int jj = 0; jj < 4; jj++) acc[i][jj] = sB1[jo + jj];
        for (int k4 = 0; k4 < 64; k4 += 4) {
            float a[4][4];
#pragma unroll
            for (int i = 0; i < 4; i++)
                *(float4*)a[i] = *(const float4*)(xs + (eo + i) * PADX + k4);
#pragma unroll
            for (int kk = 0; kk < 4; kk++) {
                float4 w = *(const float4*)(sW1 + (k4 + kk) * 64 + jo);
#pragma unroll
                for (int i = 0; i < 4; i++) {
                    acc[i][0] = fmaf(a[i][kk], w.x, acc[i][0]);
                    acc[i][1] = fmaf(a[i][kk], w.y, acc[i][1]);
                    acc[i][2] = fmaf(a[i][kk], w.z, acc[i][2]);
                    acc[i][3] = fmaf(a[i][kk], w.w, acc[i][3]);
                }
            }
        }
#pragma unroll
        for (int i = 0; i < 4; i++)
            *(float4*)(h1s + (eo + i) * PADX + jo) = make_float4(
                fmaxf(acc[i][0], 0.f), fmaxf(acc[i][1], 0.f),
                fmaxf(acc[i][2], 0.f), fmaxf(acc[i][3], 0.f));
        __syncthreads();
        for (int idx = threadIdx.x; idx < 64 * 6; idx += 256) {
            int nl = idx / 6, o = idx % 6;
            int m = m0 + nl;
            if (m < NN) {
                float s = sB2[o];
#pragma unroll 8
                for (int k = 0; k < 64; k++) s = fmaf(h1s[nl * PADX + k], sW2p[k * 8 + o], s);
                out[(size_t)m * 6 + o] = s;
            }
        }
        __syncthreads();
    }
}

// ---------------------------------------------------------------------------
extern "C" void kernel_launch(void* const* d_in, const int* in_sizes, int n_in,
                              void* d_out, int out_size)
{
    const float* x         = (const float*)d_in[0];
    const float* edge_attr = (const float*)d_in[1];
    const int*   ei        = (const int*)d_in[2];
    const float* enc_n_w1 = (const float*)d_in[3];
    const float* enc_n_b1 = (const float*)d_in[4];
    const float* enc_n_w2 = (const float*)d_in[5];
    const float* enc_n_b2 = (const float*)d_in[6];
    const float* enc_e_w1 = (const float*)d_in[7];
    const float* enc_e_b1 = (const float*)d_in[8];
    const float* enc_e_w2 = (const float*)d_in[9];
    const float* enc_e_b2 = (const float*)d_in[10];
    const float* pe_w1 = (const float*)d_in[11];
    const float* pe_b1 = (const float*)d_in[12];
    const float* pe_w2 = (const float*)d_in[13];
    const float* pe_b2 = (const float*)d_in[14];
    const float* pn_w1 = (const float*)d_in[15];
    const float* pn_b1 = (const float*)d_in[16];
    const float* pn_w2 = (const float*)d_in[17];
    const float* pn_b2 = (const float*)d_in[18];
    const float* dec_w1 = (const float*)d_in[19];
    const float* dec_b1 = (const float*)d_in[20];
    const float* dec_w2 = (const float*)d_in[21];
    const float* dec_b2 = (const float*)d_in[22];
    float* out = (float*)d_out;

    float *xh_p, *Sh_p, *Sm0_p, *Sm1_p, *deg_p, *c0_p, *c1_p;
    cudaGetSymbolAddress((void**)&xh_p,  g_xh);
    cudaGetSymbolAddress((void**)&Sh_p,  g_Sh);
    cudaGetSymbolAddress((void**)&Sm0_p, g_Sm0);
    cudaGetSymbolAddress((void**)&Sm1_p, g_Sm1);
    cudaGetSymbolAddress((void**)&deg_p, g_deg);
    cudaGetSymbolAddress((void**)&c0_p,  g_c0);
    cudaGetSymbolAddress((void**)&c1_p,  g_c1);

    const int SM_ENC_N = (4096 + 8 * 64 + 128 + 64 * 8 + 64 * PADX) * 4;
    const int SM_PQ    = (4096 * 2 + 64 + 64 * PADX) * 4;
    const int SM_E0    = (4096 + 256 + 64 + 256 + 64 * PADX + 128) * 4;
    const int SM_E1    = (4096 * 2 + 256 + 64 + 256 + 2 * 64 * PADX + 128) * 4;
    const int SM_A0    = (4096 * 2 + 64 + 2 * 64 * PADX + 64) * 4;
    const int SM_A1    = (4096 + 64 + 64 * PADX + 64) * 4;
    const int SM_NODE  = (4096 * 3 + 128 + 2 * 64 * PADX) * 4;
    const int SM_DEC   = (4096 + 512 + 72 + 2 * 64 * PADX) * 4;

    cudaFuncSetAttribute(k_encode<8>, cudaFuncAttributeMaxDynamicSharedMemorySize, SM_ENC_N);
    cudaFuncSetAttribute(k_pq,     cudaFuncAttributeMaxDynamicSharedMemorySize, SM_PQ);
    cudaFuncSetAttribute(k_edge0,  cudaFuncAttributeMaxDynamicSharedMemorySize, SM_E0);
    cudaFuncSetAttribute(k_edge1,  cudaFuncAttributeMaxDynamicSharedMemorySize, SM_E1);
    cudaFuncSetAttribute(k_agg0,   cudaFuncAttributeMaxDynamicSharedMemorySize, SM_A0);
    cudaFuncSetAttribute(k_agg1,   cudaFuncAttributeMaxDynamicSharedMemorySize, SM_A1);
    cudaFuncSetAttribute(k_node,   cudaFuncAttributeMaxDynamicSharedMemorySize, SM_NODE);
    cudaFuncSetAttribute(k_decode, cudaFuncAttributeMaxDynamicSharedMemorySize, SM_DEC);

    const int* src = ei;
    const int* dst = ei + EE;
    const size_t NB = (size_t)NN * 64 * sizeof(float);

    // zero accumulators
    cudaMemsetAsync(Sh_p,  0, NB, 0);
    cudaMemsetAsync(Sm0_p, 0, NB, 0);
    cudaMemsetAsync(Sm1_p, 0, NB, 0);
    cudaMemsetAsync(deg_p, 0, (size_t)NN * sizeof(float), 0);

    // encoders + precompute + degrees
    k_encode<8><<<782, 256, SM_ENC_N>>>(x, NN, enc_n_w1, enc_n_b1, enc_n_w2, enc_n_b2, xh_p);
    k_prep<<<3, 256>>>(enc_e_w2, enc_e_b2, pe_w1, pe_b1, pe_w2, pe_b2);
    k_deg<<<592, 256>>>(dst);

    // layer 0
    k_pq<<<592, 256, SM_PQ>>>(pe_w1 + 64 * 64, pe_w1 + 128 * 64, c0_p);
    k_edge0<<<888, 256, SM_E0>>>(src, dst, edge_attr, enc_e_w1, enc_e_b1);
    k_agg0<<<592, 256, SM_A0>>>(enc_e_w2, pe_w2);
    k_node<<<296, 256, SM_NODE>>>(pn_w1, pn_w1 + 64 * 64,
                                  pn_b1, pn_w2, pn_b2);

    // layer 1
    k_pq<<<592, 256, SM_PQ>>>(pe_w1 + 192 * 64 + 64 * 64, pe_w1 + 192 * 64 + 128 * 64, c1_p);
    k_edge1<<<444, 256, SM_E1>>>(src, dst, edge_attr, enc_e_w1, enc_e_b1);
    k_agg1<<<592, 256, SM_A1>>>(pe_w2 + 4096, pe_b2 + 64);
    k_node<<<296, 256, SM_NODE>>>(pn_w1 + 128 * 64, pn_w1 + 128 * 64 + 64 * 64,
                                  pn_b1 + 64, pn_w2 + 4096, pn_b2 + 64);

    // decode
    k_decode<<<592, 256, SM_DEC>>>(dec_w1, dec_b1, dec_w2, dec_b2, out);
}